// round 8
// baseline (speedup 1.0000x reference)
#include <cuda_runtime.h>
#include <cstdint>

// Problem constants
#define BB 4
#define TT 2048
#define EE 1024
#define HH 16
#define HD 64
#define BT (BB * TT)   // 8192 rows

// ---------------------------------------------------------------------------
// Scratch (static __device__ arrays; no runtime allocation allowed)
// ---------------------------------------------------------------------------
__device__ float g_Q[BB * HH * TT * HD];   // [b,h,t,d], q pre-scaled
__device__ float g_K[BB * HH * TT * HD];
__device__ float g_V[BB * HH * TT * HD];
__device__ float g_AO[BT * EE];            // attention output, [b,t,e]

// ---------------------------------------------------------------------------
// tf32 / cp.async helpers (all sm_80+ PTX — valid at plain sm_100 target)
// ---------------------------------------------------------------------------
__device__ __forceinline__ uint32_t f2tf32(float f) {
    uint32_t r;
    asm("cvt.rna.tf32.f32 %0, %1;" : "=r"(r) : "f"(f));
    return r;
}

__device__ __forceinline__ void mma_tf32_16x8x8(
    float& c0, float& c1, float& c2, float& c3,
    uint32_t a0, uint32_t a1, uint32_t a2, uint32_t a3,
    uint32_t b0, uint32_t b1) {
    asm volatile(
        "mma.sync.aligned.m16n8k8.row.col.f32.tf32.tf32.f32 "
        "{%0,%1,%2,%3}, {%4,%5,%6,%7}, {%8,%9}, {%0,%1,%2,%3};"
        : "+f"(c0), "+f"(c1), "+f"(c2), "+f"(c3)
        : "r"(a0), "r"(a1), "r"(a2), "r"(a3), "r"(b0), "r"(b1));
}

__device__ __forceinline__ void cp_async16(uint32_t dst_smem, const void* src) {
    asm volatile("cp.async.cg.shared.global [%0], [%1], 16;"
                 :: "r"(dst_smem), "l"(src));
}
#define CP_COMMIT() asm volatile("cp.async.commit_group;" ::: "memory")
#define CP_WAIT(N)  asm volatile("cp.async.wait_group %0;" :: "n"(N) : "memory")

// ---------------------------------------------------------------------------
// Kernel 1: tf32 mma.sync per-head QKV projection (unchanged — known correct)
// ---------------------------------------------------------------------------
#define QK_LD   68
#define QK_SMEM ((128 * QK_LD + 192 * QK_LD) * 4)   // 87040 B (dynamic)

__global__ __launch_bounds__(256, 1)
void qkv_mma_kernel(const float* __restrict__ x,
                    const float* __restrict__ Wq,
                    const float* __restrict__ bq) {
    extern __shared__ uint32_t qsm[];
    uint32_t* Xs = qsm;                   // [128][68], [r][k]
    uint32_t* Ws = qsm + 128 * QK_LD;     // [192][68], [n][k]  (transposed W)

    const int h    = blockIdx.y;
    const int row0 = blockIdx.x * 128;    // over B*T
    const int tid  = threadIdx.x;
    const int wid  = tid >> 5;
    const int lane = tid & 31;
    const int lrow = lane >> 2;           // 0..7
    const int lcol = lane & 3;            // 0..3

    const int warp_m = (wid & 1) * 64;    // 0 or 64
    const int warp_n = (wid >> 1) * 48;   // 0,48,96,144

#pragma unroll
    for (int it = 0; it < 8; it++) {
        const int i = it * 256 + tid;     // 0..2047 float4s
        const int r = i >> 4, c = (i & 15) * 4;
        const float4 v = *(const float4*)&x[(size_t)(row0 + r) * EE + h * HD + c];
        *(uint4*)&Xs[r * QK_LD + c] =
            make_uint4(f2tf32(v.x), f2tf32(v.y), f2tf32(v.z), f2tf32(v.w));
    }

    const float* Wh = Wq + (size_t)h * 64 * 192;
#pragma unroll
    for (int it = 0; it < 12; it++) {
        const int i = it * 256 + tid;     // 0..3071 float4s
        const int d = i / 48, c = (i % 48) * 4;
        const float4 v = *(const float4*)&Wh[d * 192 + c];
        Ws[(c + 0) * QK_LD + d] = f2tf32(v.x);
        Ws[(c + 1) * QK_LD + d] = f2tf32(v.y);
        Ws[(c + 2) * QK_LD + d] = f2tf32(v.z);
        Ws[(c + 3) * QK_LD + d] = f2tf32(v.w);
    }
    __syncthreads();

    float c[4][6][4];
#pragma unroll
    for (int m = 0; m < 4; m++)
#pragma unroll
        for (int n = 0; n < 6; n++)
#pragma unroll
            for (int f = 0; f < 4; f++) c[m][n][f] = 0.f;

#pragma unroll
    for (int ks = 0; ks < 8; ks++) {
        const int kk = ks * 8;
        uint32_t a[4][4], b[6][2];
#pragma unroll
        for (int m = 0; m < 4; m++) {
            const int ar = warp_m + m * 16 + lrow;
            a[m][0] = Xs[ar * QK_LD + kk + lcol];
            a[m][1] = Xs[(ar + 8) * QK_LD + kk + lcol];
            a[m][2] = Xs[ar * QK_LD + kk + 4 + lcol];
            a[m][3] = Xs[(ar + 8) * QK_LD + kk + 4 + lcol];
        }
#pragma unroll
        for (int n = 0; n < 6; n++) {
            const int br = warp_n + n * 8 + lrow;
            b[n][0] = Ws[br * QK_LD + kk + lcol];
            b[n][1] = Ws[br * QK_LD + kk + 4 + lcol];
        }
#pragma unroll
        for (int m = 0; m < 4; m++)
#pragma unroll
            for (int n = 0; n < 6; n++)
                mma_tf32_16x8x8(c[m][n][0], c[m][n][1], c[m][n][2], c[m][n][3],
                                a[m][0], a[m][1], a[m][2], a[m][3],
                                b[n][0], b[n][1]);
    }

    const float scale = (float)(1.0 / (8.0 + 1e-5));
#pragma unroll
    for (int n = 0; n < 6; n++) {
        const int col = warp_n + n * 8 + 2 * lcol;   // 0..191
        const int sec = col >> 6;                    // 0=q,1=k,2=v
        const int d   = col & 63;
        const float b0 = bq[h * 192 + col];
        const float b1 = bq[h * 192 + col + 1];
        float* dst = (sec == 0) ? g_Q : (sec == 1) ? g_K : g_V;
        const float mul = (sec == 0) ? scale : 1.0f;
#pragma unroll
        for (int m = 0; m < 4; m++) {
            const int r  = row0 + warp_m + m * 16 + lrow;
            const int b_ = r / TT;
            const int t  = r - b_ * TT;
            const size_t off = ((size_t)(b_ * HH + h) * TT + t) * HD + d;
            *(float2*)&dst[off] =
                make_float2((c[m][n][0] + b0) * mul, (c[m][n][1] + b1) * mul);
            const size_t off2 = off + (size_t)8 * HD;   // row r+8, same b_ (128 | TT)
            *(float2*)&dst[off2] =
                make_float2((c[m][n][2] + b0) * mul, (c[m][n][3] + b1) * mul);
        }
    }
}

// ---------------------------------------------------------------------------
// Kernel 2 (NEW): tf32 mma.sync causal flash attention, BM=128, 8 warps,
// cp.async double-buffered K/V (raw fp32 in smem, cvt.rna at fragment load).
// ---------------------------------------------------------------------------
#define AT_LDQ 68
#define AT_LDK 68
#define AT_LDV 72
// layout: Qs[128*68] | Ks0[64*68] | Ks1[64*68] | Vs0[64*72] | Vs1[64*72]
#define AT_OFF_K0 (128 * AT_LDQ)
#define AT_OFF_K1 (AT_OFF_K0 + 64 * AT_LDK)
#define AT_OFF_V0 (AT_OFF_K1 + 64 * AT_LDK)
#define AT_OFF_V1 (AT_OFF_V0 + 64 * AT_LDV)
#define AT_SMEM ((AT_OFF_V1 + 64 * AT_LDV) * 4)   // 106496 B

__global__ __launch_bounds__(256, 2)
void attn_mma_kernel() {
    extern __shared__ uint32_t asm_[];
    uint32_t* Qs = asm_;   // 128 x 68 (Q tile, later per-warp P buffer)

    const int bh    = blockIdx.y;
    const int qtile = gridDim.x - 1 - blockIdx.x;   // big tiles first
    const int q0    = qtile * 128;
    const int nkt   = 2 * qtile + 2;
    const float* Qp = g_Q + (size_t)bh * TT * HD;
    const float* Kp = g_K + (size_t)bh * TT * HD;
    const float* Vp = g_V + (size_t)bh * TT * HD;

    const int tid  = threadIdx.x;
    const int wid  = tid >> 5;     // 0..7
    const int lane = tid & 31;
    const int lrow = lane >> 2;
    const int lcol = lane & 3;
    const int wm   = wid * 16;     // warp row base, 0..112

    const uint32_t smem_u32 = (uint32_t)__cvta_generic_to_shared(asm_);
    const uint32_t koff[2] = { smem_u32 + AT_OFF_K0 * 4, smem_u32 + AT_OFF_K1 * 4 };
    const uint32_t voff[2] = { smem_u32 + AT_OFF_V0 * 4, smem_u32 + AT_OFF_V1 * 4 };
    uint32_t* Ksb_[2] = { asm_ + AT_OFF_K0, asm_ + AT_OFF_K1 };
    uint32_t* Vsb_[2] = { asm_ + AT_OFF_V0, asm_ + AT_OFF_V1 };

    // ---- stage Q tile 128x64 (tf32) ----
#pragma unroll
    for (int it = 0; it < 8; it++) {
        const int i = it * 256 + tid;     // 0..2047 float4s
        const int r = i >> 4, d = (i & 15) * 4;
        const float4 v = *(const float4*)&Qp[(size_t)(q0 + r) * HD + d];
        *(uint4*)&Qs[r * AT_LDQ + d] =
            make_uint4(f2tf32(v.x), f2tf32(v.y), f2tf32(v.z), f2tf32(v.w));
    }
    __syncthreads();

    uint32_t qf[8][4];
#pragma unroll
    for (int ks = 0; ks < 8; ks++) {
        const int base = (wm + lrow) * AT_LDQ + ks * 8 + lcol;
        qf[ks][0] = Qs[base];
        qf[ks][1] = Qs[base + 8 * AT_LDQ];
        qf[ks][2] = Qs[base + 4];
        qf[ks][3] = Qs[base + 8 * AT_LDQ + 4];
    }
    __syncthreads();   // Qs becomes the per-warp P buffer

    // ---- prologue: async-stage tiles 0 and 1 ----
#pragma unroll
    for (int b = 0; b < 2; b++) {
        const int kbase = b * 64;
#pragma unroll
        for (int it = 0; it < 4; it++) {
            const int i = it * 256 + tid;      // 0..1023 float4s
            const int r = i >> 4, d = (i & 15) * 4;
            cp_async16(koff[b] + (uint32_t)(r * AT_LDK + d) * 4,
                       Kp + (size_t)(kbase + r) * HD + d);
            cp_async16(voff[b] + (uint32_t)(r * AT_LDV + d) * 4,
                       Vp + (size_t)(kbase + r) * HD + d);
        }
        CP_COMMIT();
    }

    float o[8][4];
#pragma unroll
    for (int n = 0; n < 8; n++)
#pragma unroll
        for (int f = 0; f < 4; f++) o[n][f] = 0.f;
    float m0 = -1e30f, m1 = -1e30f, l0 = 0.f, l1 = 0.f;

    const int r0g = q0 + wm + lrow;
    const int r1g = r0g + 8;

    for (int kt = 0; kt < nkt; kt++) {
        if (kt < nkt - 1) { CP_WAIT(1); } else { CP_WAIT(0); }
        __syncthreads();   // tile kt visible to all warps

        const int cur = kt & 1;
        const uint32_t* Ks = Ksb_[cur];
        const uint32_t* Vs = Vsb_[cur];
        const int kbase = kt * 64;

        // warp entirely below the diagonal band of this tile -> contributes 0
        const bool active = (kbase <= q0 + wm + 15);
        if (active) {
            // ---- S = Q K^T (K raw fp32 -> cvt at load) ----
            float s[8][4];
#pragma unroll
            for (int n = 0; n < 8; n++)
#pragma unroll
                for (int f = 0; f < 4; f++) s[n][f] = 0.f;

#pragma unroll
            for (int ks = 0; ks < 8; ks++) {
                const int kk = ks * 8;
#pragma unroll
                for (int n = 0; n < 8; n++) {
                    const int kr = (n * 8 + lrow) * AT_LDK + kk + lcol;
                    const uint32_t b0 = f2tf32(__uint_as_float(Ks[kr]));
                    const uint32_t b1 = f2tf32(__uint_as_float(Ks[kr + 4]));
                    mma_tf32_16x8x8(s[n][0], s[n][1], s[n][2], s[n][3],
                                    qf[ks][0], qf[ks][1], qf[ks][2], qf[ks][3],
                                    b0, b1);
                }
            }

            if (kbase + 63 > r0g) {   // tile intersects the diagonal for this thread
#pragma unroll
                for (int n = 0; n < 8; n++) {
                    const int cg = kbase + n * 8 + 2 * lcol;
                    if (cg     > r0g) s[n][0] = -1e30f;
                    if (cg + 1 > r0g) s[n][1] = -1e30f;
                    if (cg     > r1g) s[n][2] = -1e30f;
                    if (cg + 1 > r1g) s[n][3] = -1e30f;
                }
            }

            // ---- online softmax (registers + quad shuffle) ----
            float mx0 = m0, mx1 = m1;
#pragma unroll
            for (int n = 0; n < 8; n++) {
                mx0 = fmaxf(mx0, fmaxf(s[n][0], s[n][1]));
                mx1 = fmaxf(mx1, fmaxf(s[n][2], s[n][3]));
            }
            mx0 = fmaxf(mx0, __shfl_xor_sync(0xffffffffu, mx0, 1));
            mx0 = fmaxf(mx0, __shfl_xor_sync(0xffffffffu, mx0, 2));
            mx1 = fmaxf(mx1, __shfl_xor_sync(0xffffffffu, mx1, 1));
            mx1 = fmaxf(mx1, __shfl_xor_sync(0xffffffffu, mx1, 2));

            float sum0 = 0.f, sum1 = 0.f;
#pragma unroll
            for (int n = 0; n < 8; n++) {
                s[n][0] = __expf(s[n][0] - mx0);
                s[n][1] = __expf(s[n][1] - mx0);
                s[n][2] = __expf(s[n][2] - mx1);
                s[n][3] = __expf(s[n][3] - mx1);
                sum0 += s[n][0] + s[n][1];
                sum1 += s[n][2] + s[n][3];
            }
            sum0 += __shfl_xor_sync(0xffffffffu, sum0, 1);
            sum0 += __shfl_xor_sync(0xffffffffu, sum0, 2);
            sum1 += __shfl_xor_sync(0xffffffffu, sum1, 1);
            sum1 += __shfl_xor_sync(0xffffffffu, sum1, 2);

            const float cf0 = __expf(m0 - mx0);
            const float cf1 = __expf(m1 - mx1);
            l0 = l0 * cf0 + sum0;  m0 = mx0;
            l1 = l1 * cf1 + sum1;  m1 = mx1;
#pragma unroll
            for (int n = 0; n < 8; n++) {
                o[n][0] *= cf0; o[n][1] *= cf0;
                o[n][2] *= cf1; o[n][3] *= cf1;
            }

            // ---- P -> per-warp smem rows, then PV (V cvt at load) ----
#pragma unroll
            for (int n = 0; n < 8; n++) {
                const int pr = (wm + lrow) * AT_LDQ + n * 8 + 2 * lcol;
                *(uint2*)&Qs[pr] = make_uint2(f2tf32(s[n][0]), f2tf32(s[n][1]));
                *(uint2*)&Qs[pr + 8 * AT_LDQ] = make_uint2(f2tf32(s[n][2]), f2tf32(s[n][3]));
            }
            __syncwarp();

#pragma unroll
            for (int ks = 0; ks < 8; ks++) {
                const int kk = ks * 8;
                const int pb = (wm + lrow) * AT_LDQ + kk + lcol;
                const uint32_t a0 = Qs[pb];
                const uint32_t a1 = Qs[pb + 8 * AT_LDQ];
                const uint32_t a2 = Qs[pb + 4];
                const uint32_t a3 = Qs[pb + 8 * AT_LDQ + 4];
#pragma unroll
                for (int n = 0; n < 8; n++) {
                    const uint32_t b0 = f2tf32(__uint_as_float(Vs[(kk + lcol) * AT_LDV + n * 8 + lrow]));
                    const uint32_t b1 = f2tf32(__uint_as_float(Vs[(kk + 4 + lcol) * AT_LDV + n * 8 + lrow]));
                    mma_tf32_16x8x8(o[n][0], o[n][1], o[n][2], o[n][3],
                                    a0, a1, a2, a3, b0, b1);
                }
            }
            __syncwarp();
        }

        __syncthreads();   // all warps done reading buf[cur] before refill
        if (kt + 2 < nkt) {
            const int kb2 = (kt + 2) * 64;
#pragma unroll
            for (int it = 0; it < 4; it++) {
                const int i = it * 256 + tid;
                const int r = i >> 4, d = (i & 15) * 4;
                cp_async16(koff[cur] + (uint32_t)(r * AT_LDK + d) * 4,
                           Kp + (size_t)(kb2 + r) * HD + d);
                cp_async16(voff[cur] + (uint32_t)(r * AT_LDV + d) * 4,
                           Vp + (size_t)(kb2 + r) * HD + d);
            }
            CP_COMMIT();
        }
    }

    // ---- normalize and store ----
    const float inv0 = 1.0f / l0;
    const float inv1 = 1.0f / l1;
    const int b_ = bh >> 4, h = bh & 15;
    const size_t rowbase0 = (size_t)(b_ * TT + r0g) * EE + h * HD;
    const size_t rowbase1 = (size_t)(b_ * TT + r1g) * EE + h * HD;
#pragma unroll
    for (int n = 0; n < 8; n++) {
        const int d = n * 8 + 2 * lcol;
        *(float2*)&g_AO[rowbase0 + d] = make_float2(o[n][0] * inv0, o[n][1] * inv0);
        *(float2*)&g_AO[rowbase1 + d] = make_float2(o[n][2] * inv1, o[n][3] * inv1);
    }
}

// ---------------------------------------------------------------------------
// Kernel 3: tf32 mma.sync output projection (unchanged — known correct)
// ---------------------------------------------------------------------------
#define PJ_LDA 36   // 32 + 4 pad (float4-aligned, conflict-free fragments)

__global__ __launch_bounds__(256, 1)
void proj_mma_kernel(const float* __restrict__ Wp,
                     const float* __restrict__ bp,
                     float* __restrict__ out) {
    __shared__ uint32_t As[128 * PJ_LDA];   // A tile, tf32 bits, [r][k]
    __shared__ uint32_t Bs[128 * PJ_LDA];   // B tile (=Wp rows), [n][k]

    const int tid  = threadIdx.x;
    const int wid  = tid >> 5;
    const int lane = tid & 31;
    const int row0 = blockIdx.x * 128;
    const int col0 = blockIdx.y * 128;

    const int warp_m = (wid & 1) * 64;   // 0 or 64
    const int warp_n = (wid >> 1) * 32;  // 0,32,64,96

    float c[4][4][4];   // [m16][n8][frag]
#pragma unroll
    for (int m = 0; m < 4; m++)
#pragma unroll
        for (int n = 0; n < 4; n++)
#pragma unroll
            for (int f = 0; f < 4; f++) c[m][n][f] = 0.f;

    const int lrow = lane >> 2;    // 0..7
    const int lcol = lane & 3;     // 0..3

    for (int kt = 0; kt < EE / 32; kt++) {
        const int k0 = kt * 32;
        __syncthreads();
#pragma unroll
        for (int it = 0; it < 4; it++) {
            const int lin = it * 1024 + tid * 4;   // 0..4095
            const int r = lin >> 5, cc = lin & 31;
            const float4 va = *(const float4*)&g_AO[(size_t)(row0 + r) * EE + k0 + cc];
            const float4 vb = *(const float4*)&Wp  [(size_t)(col0 + r) * EE + k0 + cc];
            *(uint4*)&As[r * PJ_LDA + cc] =
                make_uint4(f2tf32(va.x), f2tf32(va.y), f2tf32(va.z), f2tf32(va.w));
            *(uint4*)&Bs[r * PJ_LDA + cc] =
                make_uint4(f2tf32(vb.x), f2tf32(vb.y), f2tf32(vb.z), f2tf32(vb.w));
        }
        __syncthreads();

#pragma unroll
        for (int ks = 0; ks < 4; ks++) {
            const int kk = ks * 8;
            uint32_t a[4][4], b[4][2];
#pragma unroll
            for (int m = 0; m < 4; m++) {
                const int ar = warp_m + m * 16 + lrow;
                a[m][0] = As[ar * PJ_LDA + kk + lcol];
                a[m][1] = As[(ar + 8) * PJ_LDA + kk + lcol];
                a[m][2] = As[ar * PJ_LDA + kk + 4 + lcol];
                a[m][3] = As[(ar + 8) * PJ_LDA + kk + 4 + lcol];
            }
#pragma unroll
            for (int n = 0; n < 4; n++) {
                const int br = warp_n + n * 8 + lrow;
                b[n][0] = Bs[br * PJ_LDA + kk + lcol];
                b[n][1] = Bs[br * PJ_LDA + kk + 4 + lcol];
            }
#pragma unroll
            for (int m = 0; m < 4; m++)
#pragma unroll
                for (int n = 0; n < 4; n++)
                    mma_tf32_16x8x8(c[m][n][0], c[m][n][1], c[m][n][2], c[m][n][3],
                                    a[m][0], a[m][1], a[m][2], a[m][3],
                                    b[n][0], b[n][1]);
        }
    }

#pragma unroll
    for (int m = 0; m < 4; m++) {
#pragma unroll
        for (int n = 0; n < 4; n++) {
            const int col = col0 + warp_n + n * 8 + 2 * lcol;
            const int r1  = row0 + warp_m + m * 16 + lrow;
            const float b0 = bp[col], b1 = bp[col + 1];
            float2 o0 = make_float2(c[m][n][0] + b0, c[m][n][1] + b1);
            float2 o1 = make_float2(c[m][n][2] + b0, c[m][n][3] + b1);
            *(float2*)&out[(size_t)r1 * EE + col]       = o0;
            *(float2*)&out[(size_t)(r1 + 8) * EE + col] = o1;
        }
    }
}

// ---------------------------------------------------------------------------
// Launch
// ---------------------------------------------------------------------------
extern "C" void kernel_launch(void* const* d_in, const int* in_sizes, int n_in,
                              void* d_out, int out_size) {
    const float* x  = (const float*)d_in[0];
    const float* Wq = (const float*)d_in[1];
    const float* bq = (const float*)d_in[2];
    const float* Wp = (const float*)d_in[3];
    const float* bp = (const float*)d_in[4];
    float* out = (float*)d_out;

    cudaFuncSetAttribute(qkv_mma_kernel,  cudaFuncAttributeMaxDynamicSharedMemorySize, QK_SMEM);
    cudaFuncSetAttribute(attn_mma_kernel, cudaFuncAttributeMaxDynamicSharedMemorySize, AT_SMEM);

    qkv_mma_kernel<<<dim3(BT / 128, HH), 256, QK_SMEM>>>(x, Wq, bq);
    attn_mma_kernel<<<dim3(TT / 128, BB * HH), 256, AT_SMEM>>>();
    proj_mma_kernel<<<dim3(BT / 128, EE / 128), 256>>>(Wp, bp, out);
}

// round 9
// speedup vs baseline: 1.0148x; 1.0148x over previous
#include <cuda_runtime.h>
#include <cstdint>

// Problem constants
#define BB 4
#define TT 2048
#define EE 1024
#define HH 16
#define HD 64
#define BT (BB * TT)   // 8192 rows

// ---------------------------------------------------------------------------
// Scratch (static __device__ arrays; no runtime allocation allowed)
// ---------------------------------------------------------------------------
__device__ float g_Q[BB * HH * TT * HD];   // [b,h,t,d], q pre-scaled
__device__ float g_K[BB * HH * TT * HD];
__device__ float g_V[BB * HH * TT * HD];
__device__ float g_AO[BT * EE];            // attention output, [b,t,e]

// ---------------------------------------------------------------------------
// tf32 / cp.async helpers (all sm_80+ PTX — valid at plain sm_100 target)
// ---------------------------------------------------------------------------
__device__ __forceinline__ uint32_t f2tf32(float f) {
    uint32_t r;
    asm("cvt.rna.tf32.f32 %0, %1;" : "=r"(r) : "f"(f));
    return r;
}

__device__ __forceinline__ void mma_tf32_16x8x8(
    float& c0, float& c1, float& c2, float& c3,
    uint32_t a0, uint32_t a1, uint32_t a2, uint32_t a3,
    uint32_t b0, uint32_t b1) {
    asm volatile(
        "mma.sync.aligned.m16n8k8.row.col.f32.tf32.tf32.f32 "
        "{%0,%1,%2,%3}, {%4,%5,%6,%7}, {%8,%9}, {%0,%1,%2,%3};"
        : "+f"(c0), "+f"(c1), "+f"(c2), "+f"(c3)
        : "r"(a0), "r"(a1), "r"(a2), "r"(a3), "r"(b0), "r"(b1));
}

__device__ __forceinline__ void cp_async16(uint32_t dst_smem, const void* src) {
    asm volatile("cp.async.cg.shared.global [%0], [%1], 16;"
                 :: "r"(dst_smem), "l"(src));
}
#define CP_COMMIT() asm volatile("cp.async.commit_group;" ::: "memory")
#define CP_WAIT(N)  asm volatile("cp.async.wait_group %0;" :: "n"(N) : "memory")

// ---------------------------------------------------------------------------
// Kernel 1: tf32 mma.sync per-head QKV projection (unchanged — known correct)
// ---------------------------------------------------------------------------
#define QK_LD   68
#define QK_SMEM ((128 * QK_LD + 192 * QK_LD) * 4)   // 87040 B (dynamic)

__global__ __launch_bounds__(256, 1)
void qkv_mma_kernel(const float* __restrict__ x,
                    const float* __restrict__ Wq,
                    const float* __restrict__ bq) {
    extern __shared__ uint32_t qsm[];
    uint32_t* Xs = qsm;                   // [128][68], [r][k]
    uint32_t* Ws = qsm + 128 * QK_LD;     // [192][68], [n][k]  (transposed W)

    const int h    = blockIdx.y;
    const int row0 = blockIdx.x * 128;    // over B*T
    const int tid  = threadIdx.x;
    const int wid  = tid >> 5;
    const int lane = tid & 31;
    const int lrow = lane >> 2;           // 0..7
    const int lcol = lane & 3;            // 0..3

    const int warp_m = (wid & 1) * 64;    // 0 or 64
    const int warp_n = (wid >> 1) * 48;   // 0,48,96,144

#pragma unroll
    for (int it = 0; it < 8; it++) {
        const int i = it * 256 + tid;     // 0..2047 float4s
        const int r = i >> 4, c = (i & 15) * 4;
        const float4 v = *(const float4*)&x[(size_t)(row0 + r) * EE + h * HD + c];
        *(uint4*)&Xs[r * QK_LD + c] =
            make_uint4(f2tf32(v.x), f2tf32(v.y), f2tf32(v.z), f2tf32(v.w));
    }

    const float* Wh = Wq + (size_t)h * 64 * 192;
#pragma unroll
    for (int it = 0; it < 12; it++) {
        const int i = it * 256 + tid;     // 0..3071 float4s
        const int d = i / 48, c = (i % 48) * 4;
        const float4 v = *(const float4*)&Wh[d * 192 + c];
        Ws[(c + 0) * QK_LD + d] = f2tf32(v.x);
        Ws[(c + 1) * QK_LD + d] = f2tf32(v.y);
        Ws[(c + 2) * QK_LD + d] = f2tf32(v.z);
        Ws[(c + 3) * QK_LD + d] = f2tf32(v.w);
    }
    __syncthreads();

    float c[4][6][4];
#pragma unroll
    for (int m = 0; m < 4; m++)
#pragma unroll
        for (int n = 0; n < 6; n++)
#pragma unroll
            for (int f = 0; f < 4; f++) c[m][n][f] = 0.f;

#pragma unroll
    for (int ks = 0; ks < 8; ks++) {
        const int kk = ks * 8;
        uint32_t a[4][4], b[6][2];
#pragma unroll
        for (int m = 0; m < 4; m++) {
            const int ar = warp_m + m * 16 + lrow;
            a[m][0] = Xs[ar * QK_LD + kk + lcol];
            a[m][1] = Xs[(ar + 8) * QK_LD + kk + lcol];
            a[m][2] = Xs[ar * QK_LD + kk + 4 + lcol];
            a[m][3] = Xs[(ar + 8) * QK_LD + kk + 4 + lcol];
        }
#pragma unroll
        for (int n = 0; n < 6; n++) {
            const int br = warp_n + n * 8 + lrow;
            b[n][0] = Ws[br * QK_LD + kk + lcol];
            b[n][1] = Ws[br * QK_LD + kk + 4 + lcol];
        }
#pragma unroll
        for (int m = 0; m < 4; m++)
#pragma unroll
            for (int n = 0; n < 6; n++)
                mma_tf32_16x8x8(c[m][n][0], c[m][n][1], c[m][n][2], c[m][n][3],
                                a[m][0], a[m][1], a[m][2], a[m][3],
                                b[n][0], b[n][1]);
    }

    const float scale = (float)(1.0 / (8.0 + 1e-5));
#pragma unroll
    for (int n = 0; n < 6; n++) {
        const int col = warp_n + n * 8 + 2 * lcol;   // 0..191
        const int sec = col >> 6;                    // 0=q,1=k,2=v
        const int d   = col & 63;
        const float b0 = bq[h * 192 + col];
        const float b1 = bq[h * 192 + col + 1];
        float* dst = (sec == 0) ? g_Q : (sec == 1) ? g_K : g_V;
        const float mul = (sec == 0) ? scale : 1.0f;
#pragma unroll
        for (int m = 0; m < 4; m++) {
            const int r  = row0 + warp_m + m * 16 + lrow;
            const int b_ = r / TT;
            const int t  = r - b_ * TT;
            const size_t off = ((size_t)(b_ * HH + h) * TT + t) * HD + d;
            *(float2*)&dst[off] =
                make_float2((c[m][n][0] + b0) * mul, (c[m][n][1] + b1) * mul);
            const size_t off2 = off + (size_t)8 * HD;   // row r+8, same b_ (128 | TT)
            *(float2*)&dst[off2] =
                make_float2((c[m][n][2] + b0) * mul, (c[m][n][3] + b1) * mul);
        }
    }
}

// ---------------------------------------------------------------------------
// Kernel 2 (R9): tf32 mma.sync causal flash attention.
//   R7 shape (BM=64, 128 threads, 4 warps, occ 2) + cp.async double-buffered
//   K/V (raw fp32 in smem, cvt.rna at fragment load — numerics identical).
// ---------------------------------------------------------------------------
#define AT_LDQ 68
#define AT_LDK 68
#define AT_LDV 72
// words: Qs[64*68] | K0[64*68] | K1[64*68] | V0[64*72] | V1[64*72]
#define AT_OFF_K0 (64 * AT_LDQ)
#define AT_OFF_K1 (AT_OFF_K0 + 64 * AT_LDK)
#define AT_OFF_V0 (AT_OFF_K1 + 64 * AT_LDK)
#define AT_OFF_V1 (AT_OFF_V0 + 64 * AT_LDV)
#define AT_SMEM ((AT_OFF_V1 + 64 * AT_LDV) * 4)   // 89088 B

__global__ __launch_bounds__(128, 2)
void attn_mma_kernel() {
    extern __shared__ uint32_t asm_[];
    uint32_t* Qs = asm_;   // 64 x 68 (Q tile, later P buffer)

    const int bh = blockIdx.y;
    const int qt = gridDim.x - 1 - blockIdx.x;    // big tiles first
    const int q0 = qt * 64;
    const float* Qp = g_Q + (size_t)bh * TT * HD;
    const float* Kp = g_K + (size_t)bh * TT * HD;
    const float* Vp = g_V + (size_t)bh * TT * HD;

    const int tid  = threadIdx.x;
    const int wid  = tid >> 5;
    const int lane = tid & 31;
    const int lrow = lane >> 2;    // 0..7
    const int lcol = lane & 3;     // 0..3
    const int wm   = wid * 16;     // warp's row base within tile

    const uint32_t smem_u32 = (uint32_t)__cvta_generic_to_shared(asm_);
    const uint32_t koff[2] = { smem_u32 + AT_OFF_K0 * 4, smem_u32 + AT_OFF_K1 * 4 };
    const uint32_t voff[2] = { smem_u32 + AT_OFF_V0 * 4, smem_u32 + AT_OFF_V1 * 4 };
    uint32_t* Ksb_[2] = { asm_ + AT_OFF_K0, asm_ + AT_OFF_K1 };
    uint32_t* Vsb_[2] = { asm_ + AT_OFF_V0, asm_ + AT_OFF_V1 };

    // ---- prologue: async-stage K/V tiles 0 and 1 (if they exist) ----
#pragma unroll
    for (int b = 0; b < 2; b++) {
        if (b <= qt) {
            const int kbase = b * 64;
#pragma unroll
            for (int it = 0; it < 8; it++) {
                const int i = it * 128 + tid;      // 0..1023 float4s
                const int r = i >> 4, d = (i & 15) * 4;
                cp_async16(koff[b] + (uint32_t)(r * AT_LDK + d) * 4,
                           Kp + (size_t)(kbase + r) * HD + d);
                cp_async16(voff[b] + (uint32_t)(r * AT_LDV + d) * 4,
                           Vp + (size_t)(kbase + r) * HD + d);
            }
        }
        CP_COMMIT();   // empty group is legal when tile b doesn't exist
    }

    // ---- stage Q tile (tf32) and load fragments into registers ----
#pragma unroll
    for (int it = 0; it < 8; it++) {
        const int i = it * 512 + tid * 4;         // 0..4095
        const int r = i >> 6, d = i & 63;
        const float4 v = *(const float4*)&Qp[(size_t)(q0 + r) * HD + d];
        *(uint4*)&Qs[r * AT_LDQ + d] =
            make_uint4(f2tf32(v.x), f2tf32(v.y), f2tf32(v.z), f2tf32(v.w));
    }
    __syncthreads();

    uint32_t qf[8][4];
#pragma unroll
    for (int ks = 0; ks < 8; ks++) {
        const int base = (wm + lrow) * AT_LDQ + ks * 8 + lcol;
        qf[ks][0] = Qs[base];
        qf[ks][1] = Qs[base + 8 * AT_LDQ];
        qf[ks][2] = Qs[base + 4];
        qf[ks][3] = Qs[base + 8 * AT_LDQ + 4];
    }
    __syncthreads();   // Qs becomes the P buffer from here on

    float o[8][4];
#pragma unroll
    for (int n = 0; n < 8; n++)
#pragma unroll
        for (int f = 0; f < 4; f++) o[n][f] = 0.f;
    float m0 = -1e30f, m1 = -1e30f, l0 = 0.f, l1 = 0.f;

    const int r0g = q0 + wm + lrow;     // global row of frag-half 0
    const int r1g = r0g + 8;

    for (int kt = 0; kt <= qt; kt++) {
        if (kt < qt) { CP_WAIT(1); } else { CP_WAIT(0); }
        __syncthreads();               // tile kt visible; prev compute done

        const int cur = kt & 1;
        const uint32_t* Ks = Ksb_[cur];
        const uint32_t* Vs = Vsb_[cur];
        const int kbase = kt * 64;

        // ---- S = Q K^T (K raw fp32 -> cvt at fragment load) ----
        float s[8][4];
#pragma unroll
        for (int n = 0; n < 8; n++)
#pragma unroll
            for (int f = 0; f < 4; f++) s[n][f] = 0.f;

#pragma unroll
        for (int ks = 0; ks < 8; ks++) {
            const int kk = ks * 8;
#pragma unroll
            for (int n = 0; n < 8; n++) {
                const int kr = (n * 8 + lrow) * AT_LDK + kk + lcol;
                const uint32_t b0 = f2tf32(__uint_as_float(Ks[kr]));
                const uint32_t b1 = f2tf32(__uint_as_float(Ks[kr + 4]));
                mma_tf32_16x8x8(s[n][0], s[n][1], s[n][2], s[n][3],
                                qf[ks][0], qf[ks][1], qf[ks][2], qf[ks][3],
                                b0, b1);
            }
        }

        if (kt == qt) {   // causal mask on diagonal tile
#pragma unroll
            for (int n = 0; n < 8; n++) {
                const int cg = kbase + n * 8 + 2 * lcol;
                if (cg     > r0g) s[n][0] = -1e30f;
                if (cg + 1 > r0g) s[n][1] = -1e30f;
                if (cg     > r1g) s[n][2] = -1e30f;
                if (cg + 1 > r1g) s[n][3] = -1e30f;
            }
        }

        // ---- online softmax (registers + quad shuffle) ----
        float mx0 = m0, mx1 = m1;
#pragma unroll
        for (int n = 0; n < 8; n++) {
            mx0 = fmaxf(mx0, fmaxf(s[n][0], s[n][1]));
            mx1 = fmaxf(mx1, fmaxf(s[n][2], s[n][3]));
        }
        mx0 = fmaxf(mx0, __shfl_xor_sync(0xffffffffu, mx0, 1));
        mx0 = fmaxf(mx0, __shfl_xor_sync(0xffffffffu, mx0, 2));
        mx1 = fmaxf(mx1, __shfl_xor_sync(0xffffffffu, mx1, 1));
        mx1 = fmaxf(mx1, __shfl_xor_sync(0xffffffffu, mx1, 2));

        float sum0 = 0.f, sum1 = 0.f;
#pragma unroll
        for (int n = 0; n < 8; n++) {
            s[n][0] = __expf(s[n][0] - mx0);
            s[n][1] = __expf(s[n][1] - mx0);
            s[n][2] = __expf(s[n][2] - mx1);
            s[n][3] = __expf(s[n][3] - mx1);
            sum0 += s[n][0] + s[n][1];
            sum1 += s[n][2] + s[n][3];
        }
        sum0 += __shfl_xor_sync(0xffffffffu, sum0, 1);
        sum0 += __shfl_xor_sync(0xffffffffu, sum0, 2);
        sum1 += __shfl_xor_sync(0xffffffffu, sum1, 1);
        sum1 += __shfl_xor_sync(0xffffffffu, sum1, 2);

        const float cf0 = __expf(m0 - mx0);
        const float cf1 = __expf(m1 - mx1);
        l0 = l0 * cf0 + sum0;  m0 = mx0;
        l1 = l1 * cf1 + sum1;  m1 = mx1;
#pragma unroll
        for (int n = 0; n < 8; n++) {
            o[n][0] *= cf0; o[n][1] *= cf0;
            o[n][2] *= cf1; o[n][3] *= cf1;
        }

        // ---- P -> per-warp smem rows, then PV (V cvt at load) ----
#pragma unroll
        for (int n = 0; n < 8; n++) {
            const int pr = (wm + lrow) * AT_LDQ + n * 8 + 2 * lcol;
            *(uint2*)&Qs[pr] = make_uint2(f2tf32(s[n][0]), f2tf32(s[n][1]));
            *(uint2*)&Qs[pr + 8 * AT_LDQ] = make_uint2(f2tf32(s[n][2]), f2tf32(s[n][3]));
        }
        __syncwarp();

#pragma unroll
        for (int ks = 0; ks < 8; ks++) {
            const int kk = ks * 8;
            const int pb = (wm + lrow) * AT_LDQ + kk + lcol;
            const uint32_t a0 = Qs[pb];
            const uint32_t a1 = Qs[pb + 8 * AT_LDQ];
            const uint32_t a2 = Qs[pb + 4];
            const uint32_t a3 = Qs[pb + 8 * AT_LDQ + 4];
#pragma unroll
            for (int n = 0; n < 8; n++) {
                const uint32_t b0 = f2tf32(__uint_as_float(Vs[(kk + lcol) * AT_LDV + n * 8 + lrow]));
                const uint32_t b1 = f2tf32(__uint_as_float(Vs[(kk + 4 + lcol) * AT_LDV + n * 8 + lrow]));
                mma_tf32_16x8x8(o[n][0], o[n][1], o[n][2], o[n][3],
                                a0, a1, a2, a3, b0, b1);
            }
        }

        __syncthreads();   // all warps done reading buf[cur] before refill
        if (kt + 2 <= qt) {
            const int kb2 = (kt + 2) * 64;
#pragma unroll
            for (int it = 0; it < 8; it++) {
                const int i = it * 128 + tid;
                const int r = i >> 4, d = (i & 15) * 4;
                cp_async16(koff[cur] + (uint32_t)(r * AT_LDK + d) * 4,
                           Kp + (size_t)(kb2 + r) * HD + d);
                cp_async16(voff[cur] + (uint32_t)(r * AT_LDV + d) * 4,
                           Vp + (size_t)(kb2 + r) * HD + d);
            }
        }
        CP_COMMIT();   // keep group count aligned with kt (empty group ok)
    }

    // ---- normalize and store ----
    const float inv0 = 1.0f / l0;
    const float inv1 = 1.0f / l1;
    const int b_ = bh >> 4, h = bh & 15;
    const size_t rowbase0 = (size_t)(b_ * TT + r0g) * EE + h * HD;
    const size_t rowbase1 = (size_t)(b_ * TT + r1g) * EE + h * HD;
#pragma unroll
    for (int n = 0; n < 8; n++) {
        const int d = n * 8 + 2 * lcol;
        *(float2*)&g_AO[rowbase0 + d] = make_float2(o[n][0] * inv0, o[n][1] * inv0);
        *(float2*)&g_AO[rowbase1 + d] = make_float2(o[n][2] * inv1, o[n][3] * inv1);
    }
}

// ---------------------------------------------------------------------------
// Kernel 3: tf32 mma.sync output projection (unchanged — known correct)
// ---------------------------------------------------------------------------
#define PJ_LDA 36   // 32 + 4 pad (float4-aligned, conflict-free fragments)

__global__ __launch_bounds__(256, 1)
void proj_mma_kernel(const float* __restrict__ Wp,
                     const float* __restrict__ bp,
                     float* __restrict__ out) {
    __shared__ uint32_t As[128 * PJ_LDA];   // A tile, tf32 bits, [r][k]
    __shared__ uint32_t Bs[128 * PJ_LDA];   // B tile (=Wp rows), [n][k]

    const int tid  = threadIdx.x;
    const int wid  = tid >> 5;
    const int lane = tid & 31;
    const int row0 = blockIdx.x * 128;
    const int col0 = blockIdx.y * 128;

    const int warp_m = (wid & 1) * 64;   // 0 or 64
    const int warp_n = (wid >> 1) * 32;  // 0,32,64,96

    float c[4][4][4];   // [m16][n8][frag]
#pragma unroll
    for (int m = 0; m < 4; m++)
#pragma unroll
        for (int n = 0; n < 4; n++)
#pragma unroll
            for (int f = 0; f < 4; f++) c[m][n][f] = 0.f;

    const int lrow = lane >> 2;    // 0..7
    const int lcol = lane & 3;     // 0..3

    for (int kt = 0; kt < EE / 32; kt++) {
        const int k0 = kt * 32;
        __syncthreads();
#pragma unroll
        for (int it = 0; it < 4; it++) {
            const int lin = it * 1024 + tid * 4;   // 0..4095
            const int r = lin >> 5, cc = lin & 31;
            const float4 va = *(const float4*)&g_AO[(size_t)(row0 + r) * EE + k0 + cc];
            const float4 vb = *(const float4*)&Wp  [(size_t)(col0 + r) * EE + k0 + cc];
            *(uint4*)&As[r * PJ_LDA + cc] =
                make_uint4(f2tf32(va.x), f2tf32(va.y), f2tf32(va.z), f2tf32(va.w));
            *(uint4*)&Bs[r * PJ_LDA + cc] =
                make_uint4(f2tf32(vb.x), f2tf32(vb.y), f2tf32(vb.z), f2tf32(vb.w));
        }
        __syncthreads();

#pragma unroll
        for (int ks = 0; ks < 4; ks++) {
            const int kk = ks * 8;
            uint32_t a[4][4], b[4][2];
#pragma unroll
            for (int m = 0; m < 4; m++) {
                const int ar = warp_m + m * 16 + lrow;
                a[m][0] = As[ar * PJ_LDA + kk + lcol];
                a[m][1] = As[(ar + 8) * PJ_LDA + kk + lcol];
                a[m][2] = As[ar * PJ_LDA + kk + 4 + lcol];
                a[m][3] = As[(ar + 8) * PJ_LDA + kk + 4 + lcol];
            }
#pragma unroll
            for (int n = 0; n < 4; n++) {
                const int br = warp_n + n * 8 + lrow;
                b[n][0] = Bs[br * PJ_LDA + kk + lcol];
                b[n][1] = Bs[br * PJ_LDA + kk + 4 + lcol];
            }
#pragma unroll
            for (int m = 0; m < 4; m++)
#pragma unroll
                for (int n = 0; n < 4; n++)
                    mma_tf32_16x8x8(c[m][n][0], c[m][n][1], c[m][n][2], c[m][n][3],
                                    a[m][0], a[m][1], a[m][2], a[m][3],
                                    b[n][0], b[n][1]);
        }
    }

#pragma unroll
    for (int m = 0; m < 4; m++) {
#pragma unroll
        for (int n = 0; n < 4; n++) {
            const int col = col0 + warp_n + n * 8 + 2 * lcol;
            const int r1  = row0 + warp_m + m * 16 + lrow;
            const float b0 = bp[col], b1 = bp[col + 1];
            float2 o0 = make_float2(c[m][n][0] + b0, c[m][n][1] + b1);
            float2 o1 = make_float2(c[m][n][2] + b0, c[m][n][3] + b1);
            *(float2*)&out[(size_t)r1 * EE + col]       = o0;
            *(float2*)&out[(size_t)(r1 + 8) * EE + col] = o1;
        }
    }
}

// ---------------------------------------------------------------------------
// Launch
// ---------------------------------------------------------------------------
extern "C" void kernel_launch(void* const* d_in, const int* in_sizes, int n_in,
                              void* d_out, int out_size) {
    const float* x  = (const float*)d_in[0];
    const float* Wq = (const float*)d_in[1];
    const float* bq = (const float*)d_in[2];
    const float* Wp = (const float*)d_in[3];
    const float* bp = (const float*)d_in[4];
    float* out = (float*)d_out;

    cudaFuncSetAttribute(qkv_mma_kernel,  cudaFuncAttributeMaxDynamicSharedMemorySize, QK_SMEM);
    cudaFuncSetAttribute(attn_mma_kernel, cudaFuncAttributeMaxDynamicSharedMemorySize, AT_SMEM);

    qkv_mma_kernel<<<dim3(BT / 128, HH), 256, QK_SMEM>>>(x, Wq, bq);
    attn_mma_kernel<<<dim3(TT / 64, BB * HH), 128, AT_SMEM>>>();
    proj_mma_kernel<<<dim3(BT / 128, EE / 128), 256>>>(Wp, bp, out);
}

// round 11
// speedup vs baseline: 1.1463x; 1.1296x over previous
#include <cuda_runtime.h>
#include <cstdint>

// Problem constants
#define BB 4
#define TT 2048
#define EE 1024
#define HH 16
#define HD 64
#define BT (BB * TT)   // 8192 rows

// ---------------------------------------------------------------------------
// Scratch (static __device__ arrays; no runtime allocation allowed)
// ---------------------------------------------------------------------------
__device__ float g_Q[BB * HH * TT * HD];   // [b,h,t,d], q pre-scaled
__device__ float g_K[BB * HH * TT * HD];
__device__ float g_V[BB * HH * TT * HD];
__device__ float g_AO[BT * EE];            // attention output, [b,t,e]

// ---------------------------------------------------------------------------
// tf32 / cp.async helpers (all sm_80+ PTX — valid at plain sm_100 target)
// ---------------------------------------------------------------------------
__device__ __forceinline__ uint32_t f2tf32(float f) {
    uint32_t r;
    asm("cvt.rna.tf32.f32 %0, %1;" : "=r"(r) : "f"(f));
    return r;
}

__device__ __forceinline__ void mma_tf32_16x8x8(
    float& c0, float& c1, float& c2, float& c3,
    uint32_t a0, uint32_t a1, uint32_t a2, uint32_t a3,
    uint32_t b0, uint32_t b1) {
    asm volatile(
        "mma.sync.aligned.m16n8k8.row.col.f32.tf32.tf32.f32 "
        "{%0,%1,%2,%3}, {%4,%5,%6,%7}, {%8,%9}, {%0,%1,%2,%3};"
        : "+f"(c0), "+f"(c1), "+f"(c2), "+f"(c3)
        : "r"(a0), "r"(a1), "r"(a2), "r"(a3), "r"(b0), "r"(b1));
}

__device__ __forceinline__ void cp_async16(uint32_t dst_smem, const void* src) {
    asm volatile("cp.async.cg.shared.global [%0], [%1], 16;"
                 :: "r"(dst_smem), "l"(src));
}
#define CP_COMMIT() asm volatile("cp.async.commit_group;" ::: "memory")
#define CP_WAIT(N)  asm volatile("cp.async.wait_group %0;" :: "n"(N) : "memory")

// ---------------------------------------------------------------------------
// Kernel 1: tf32 mma.sync per-head QKV projection (unchanged — known correct)
// ---------------------------------------------------------------------------
#define QK_LD   68
#define QK_SMEM ((128 * QK_LD + 192 * QK_LD) * 4)   // 87040 B (dynamic)

__global__ __launch_bounds__(256, 1)
void qkv_mma_kernel(const float* __restrict__ x,
                    const float* __restrict__ Wq,
                    const float* __restrict__ bq) {
    extern __shared__ uint32_t qsm[];
    uint32_t* Xs = qsm;                   // [128][68], [r][k]
    uint32_t* Ws = qsm + 128 * QK_LD;     // [192][68], [n][k]  (transposed W)

    const int h    = blockIdx.y;
    const int row0 = blockIdx.x * 128;    // over B*T
    const int tid  = threadIdx.x;
    const int wid  = tid >> 5;
    const int lane = tid & 31;
    const int lrow = lane >> 2;           // 0..7
    const int lcol = lane & 3;            // 0..3

    const int warp_m = (wid & 1) * 64;    // 0 or 64
    const int warp_n = (wid >> 1) * 48;   // 0,48,96,144

#pragma unroll
    for (int it = 0; it < 8; it++) {
        const int i = it * 256 + tid;     // 0..2047 float4s
        const int r = i >> 4, c = (i & 15) * 4;
        const float4 v = *(const float4*)&x[(size_t)(row0 + r) * EE + h * HD + c];
        *(uint4*)&Xs[r * QK_LD + c] =
            make_uint4(f2tf32(v.x), f2tf32(v.y), f2tf32(v.z), f2tf32(v.w));
    }

    const float* Wh = Wq + (size_t)h * 64 * 192;
#pragma unroll
    for (int it = 0; it < 12; it++) {
        const int i = it * 256 + tid;     // 0..3071 float4s
        const int d = i / 48, c = (i % 48) * 4;
        const float4 v = *(const float4*)&Wh[d * 192 + c];
        Ws[(c + 0) * QK_LD + d] = f2tf32(v.x);
        Ws[(c + 1) * QK_LD + d] = f2tf32(v.y);
        Ws[(c + 2) * QK_LD + d] = f2tf32(v.z);
        Ws[(c + 3) * QK_LD + d] = f2tf32(v.w);
    }
    __syncthreads();

    float c[4][6][4];
#pragma unroll
    for (int m = 0; m < 4; m++)
#pragma unroll
        for (int n = 0; n < 6; n++)
#pragma unroll
            for (int f = 0; f < 4; f++) c[m][n][f] = 0.f;

#pragma unroll
    for (int ks = 0; ks < 8; ks++) {
        const int kk = ks * 8;
        uint32_t a[4][4], b[6][2];
#pragma unroll
        for (int m = 0; m < 4; m++) {
            const int ar = warp_m + m * 16 + lrow;
            a[m][0] = Xs[ar * QK_LD + kk + lcol];
            a[m][1] = Xs[(ar + 8) * QK_LD + kk + lcol];
            a[m][2] = Xs[ar * QK_LD + kk + 4 + lcol];
            a[m][3] = Xs[(ar + 8) * QK_LD + kk + 4 + lcol];
        }
#pragma unroll
        for (int n = 0; n < 6; n++) {
            const int br = warp_n + n * 8 + lrow;
            b[n][0] = Ws[br * QK_LD + kk + lcol];
            b[n][1] = Ws[br * QK_LD + kk + 4 + lcol];
        }
#pragma unroll
        for (int m = 0; m < 4; m++)
#pragma unroll
            for (int n = 0; n < 6; n++)
                mma_tf32_16x8x8(c[m][n][0], c[m][n][1], c[m][n][2], c[m][n][3],
                                a[m][0], a[m][1], a[m][2], a[m][3],
                                b[n][0], b[n][1]);
    }

    const float scale = (float)(1.0 / (8.0 + 1e-5));
#pragma unroll
    for (int n = 0; n < 6; n++) {
        const int col = warp_n + n * 8 + 2 * lcol;   // 0..191
        const int sec = col >> 6;                    // 0=q,1=k,2=v
        const int d   = col & 63;
        const float b0 = bq[h * 192 + col];
        const float b1 = bq[h * 192 + col + 1];
        float* dst = (sec == 0) ? g_Q : (sec == 1) ? g_K : g_V;
        const float mul = (sec == 0) ? scale : 1.0f;
#pragma unroll
        for (int m = 0; m < 4; m++) {
            const int r  = row0 + warp_m + m * 16 + lrow;
            const int b_ = r / TT;
            const int t  = r - b_ * TT;
            const size_t off = ((size_t)(b_ * HH + h) * TT + t) * HD + d;
            *(float2*)&dst[off] =
                make_float2((c[m][n][0] + b0) * mul, (c[m][n][1] + b1) * mul);
            const size_t off2 = off + (size_t)8 * HD;   // row r+8, same b_ (128 | TT)
            *(float2*)&dst[off2] =
                make_float2((c[m][n][2] + b0) * mul, (c[m][n][3] + b1) * mul);
        }
    }
}

// ---------------------------------------------------------------------------
// Kernel 2: tf32 mma.sync causal flash attention — R7 VERBATIM (645 µs config:
// BM=64, 128 threads, 4 warps, occ 4 = 16 warps/SM, sync staging).
// ---------------------------------------------------------------------------
#define AT_LDQ 68   // Qs / P stride (uint32 elems)
#define AT_LDK 68   // Ks stride
#define AT_LDV 72   // Vs stride
#define AT_SMEM ((64 * AT_LDQ + 64 * AT_LDK + 64 * AT_LDV) * 4)   // 53248 B

__global__ __launch_bounds__(128, 4)
void attn_mma_kernel() {
    extern __shared__ uint32_t asm_[];
    uint32_t* Qs = asm_;                          // 64 x 68 (Q tile, later P)
    uint32_t* Ks = Qs + 64 * AT_LDQ;              // 64 x 68, [c][d]
    uint32_t* Vs = Ks + 64 * AT_LDK;              // 64 x 72, [c][d]

    const int bh = blockIdx.y;
    const int qt = gridDim.x - 1 - blockIdx.x;    // big tiles first
    const int q0 = qt * 64;
    const float* Qp = g_Q + (size_t)bh * TT * HD;
    const float* Kp = g_K + (size_t)bh * TT * HD;
    const float* Vp = g_V + (size_t)bh * TT * HD;

    const int tid  = threadIdx.x;
    const int wid  = tid >> 5;
    const int lane = tid & 31;
    const int lrow = lane >> 2;    // 0..7
    const int lcol = lane & 3;     // 0..3
    const int wm   = wid * 16;     // warp's row base within tile

    // ---- stage Q tile (tf32) and load fragments into registers ----
#pragma unroll
    for (int it = 0; it < 8; it++) {
        const int i = it * 512 + tid * 4;         // 0..4095
        const int r = i >> 6, d = i & 63;
        const float4 v = *(const float4*)&Qp[(size_t)(q0 + r) * HD + d];
        *(uint4*)&Qs[r * AT_LDQ + d] =
            make_uint4(f2tf32(v.x), f2tf32(v.y), f2tf32(v.z), f2tf32(v.w));
    }
    __syncthreads();

    uint32_t qf[8][4];
#pragma unroll
    for (int ks = 0; ks < 8; ks++) {
        const int base = (wm + lrow) * AT_LDQ + ks * 8 + lcol;
        qf[ks][0] = Qs[base];
        qf[ks][1] = Qs[base + 8 * AT_LDQ];
        qf[ks][2] = Qs[base + 4];
        qf[ks][3] = Qs[base + 8 * AT_LDQ + 4];
    }
    __syncthreads();   // Qs becomes the P buffer from here on

    float o[8][4];
#pragma unroll
    for (int n = 0; n < 8; n++)
#pragma unroll
        for (int f = 0; f < 4; f++) o[n][f] = 0.f;
    float m0 = -1e30f, m1 = -1e30f, l0 = 0.f, l1 = 0.f;

    const int r0g = q0 + wm + lrow;     // global row of frag-half 0
    const int r1g = r0g + 8;

    for (int kt = 0; kt <= qt; kt++) {
        const int kbase = kt * 64;
        __syncthreads();               // prev PV done with Ks/Vs
#pragma unroll
        for (int it = 0; it < 8; it++) {
            const int i = it * 512 + tid * 4;
            const int r = i >> 6, d = i & 63;
            const float4 kv = *(const float4*)&Kp[(size_t)(kbase + r) * HD + d];
            const float4 vv = *(const float4*)&Vp[(size_t)(kbase + r) * HD + d];
            *(uint4*)&Ks[r * AT_LDK + d] =
                make_uint4(f2tf32(kv.x), f2tf32(kv.y), f2tf32(kv.z), f2tf32(kv.w));
            *(uint4*)&Vs[r * AT_LDV + d] =
                make_uint4(f2tf32(vv.x), f2tf32(vv.y), f2tf32(vv.z), f2tf32(vv.w));
        }
        __syncthreads();

        // ---- S = Q K^T ----
        float s[8][4];
#pragma unroll
        for (int n = 0; n < 8; n++)
#pragma unroll
            for (int f = 0; f < 4; f++) s[n][f] = 0.f;

#pragma unroll
        for (int ks = 0; ks < 8; ks++) {
            const int kk = ks * 8;
#pragma unroll
            for (int n = 0; n < 8; n++) {
                const int kr = (n * 8 + lrow) * AT_LDK + kk + lcol;
                const uint32_t b0 = Ks[kr];
                const uint32_t b1 = Ks[kr + 4];
                mma_tf32_16x8x8(s[n][0], s[n][1], s[n][2], s[n][3],
                                qf[ks][0], qf[ks][1], qf[ks][2], qf[ks][3],
                                b0, b1);
            }
        }

        if (kt == qt) {   // causal mask on diagonal tile
#pragma unroll
            for (int n = 0; n < 8; n++) {
                const int cg = kbase + n * 8 + 2 * lcol;
                if (cg     > r0g) s[n][0] = -1e30f;
                if (cg + 1 > r0g) s[n][1] = -1e30f;
                if (cg     > r1g) s[n][2] = -1e30f;
                if (cg + 1 > r1g) s[n][3] = -1e30f;
            }
        }

        // ---- online softmax (register + quad shuffle) ----
        float mx0 = m0, mx1 = m1;
#pragma unroll
        for (int n = 0; n < 8; n++) {
            mx0 = fmaxf(mx0, fmaxf(s[n][0], s[n][1]));
            mx1 = fmaxf(mx1, fmaxf(s[n][2], s[n][3]));
        }
        mx0 = fmaxf(mx0, __shfl_xor_sync(0xffffffffu, mx0, 1));
        mx0 = fmaxf(mx0, __shfl_xor_sync(0xffffffffu, mx0, 2));
        mx1 = fmaxf(mx1, __shfl_xor_sync(0xffffffffu, mx1, 1));
        mx1 = fmaxf(mx1, __shfl_xor_sync(0xffffffffu, mx1, 2));

        float sum0 = 0.f, sum1 = 0.f;
#pragma unroll
        for (int n = 0; n < 8; n++) {
            s[n][0] = __expf(s[n][0] - mx0);
            s[n][1] = __expf(s[n][1] - mx0);
            s[n][2] = __expf(s[n][2] - mx1);
            s[n][3] = __expf(s[n][3] - mx1);
            sum0 += s[n][0] + s[n][1];
            sum1 += s[n][2] + s[n][3];
        }
        sum0 += __shfl_xor_sync(0xffffffffu, sum0, 1);
        sum0 += __shfl_xor_sync(0xffffffffu, sum0, 2);
        sum1 += __shfl_xor_sync(0xffffffffu, sum1, 1);
        sum1 += __shfl_xor_sync(0xffffffffu, sum1, 2);

        const float cf0 = __expf(m0 - mx0);
        const float cf1 = __expf(m1 - mx1);
        l0 = l0 * cf0 + sum0;  m0 = mx0;
        l1 = l1 * cf1 + sum1;  m1 = mx1;
#pragma unroll
        for (int n = 0; n < 8; n++) {
            o[n][0] *= cf0; o[n][1] *= cf0;
            o[n][2] *= cf1; o[n][3] *= cf1;
        }

        // ---- P -> smem (per-warp region of Qs), then PV mma ----
#pragma unroll
        for (int n = 0; n < 8; n++) {
            const int pr = (wm + lrow) * AT_LDQ + n * 8 + 2 * lcol;
            *(uint2*)&Qs[pr] = make_uint2(f2tf32(s[n][0]), f2tf32(s[n][1]));
            *(uint2*)&Qs[pr + 8 * AT_LDQ] = make_uint2(f2tf32(s[n][2]), f2tf32(s[n][3]));
        }
        __syncwarp();

#pragma unroll
        for (int ks = 0; ks < 8; ks++) {
            const int kk = ks * 8;
            const int pb = (wm + lrow) * AT_LDQ + kk + lcol;
            const uint32_t a0 = Qs[pb];
            const uint32_t a1 = Qs[pb + 8 * AT_LDQ];
            const uint32_t a2 = Qs[pb + 4];
            const uint32_t a3 = Qs[pb + 8 * AT_LDQ + 4];
#pragma unroll
            for (int n = 0; n < 8; n++) {
                const uint32_t b0 = Vs[(kk + lcol) * AT_LDV + n * 8 + lrow];
                const uint32_t b1 = Vs[(kk + 4 + lcol) * AT_LDV + n * 8 + lrow];
                mma_tf32_16x8x8(o[n][0], o[n][1], o[n][2], o[n][3],
                                a0, a1, a2, a3, b0, b1);
            }
        }
        __syncwarp();
    }

    // ---- normalize and store ----
    const float inv0 = 1.0f / l0;
    const float inv1 = 1.0f / l1;
    const int b_ = bh >> 4, h = bh & 15;
    const size_t rowbase0 = (size_t)(b_ * TT + r0g) * EE + h * HD;
    const size_t rowbase1 = (size_t)(b_ * TT + r1g) * EE + h * HD;
#pragma unroll
    for (int n = 0; n < 8; n++) {
        const int d = n * 8 + 2 * lcol;
        *(float2*)&g_AO[rowbase0 + d] = make_float2(o[n][0] * inv0, o[n][1] * inv0);
        *(float2*)&g_AO[rowbase1 + d] = make_float2(o[n][2] * inv1, o[n][3] * inv1);
    }
}

// ---------------------------------------------------------------------------
// Kernel 3 (R10/R11): tf32 mma.sync output projection, cp.async double-buffered.
//   Tiles stream as raw fp32; cvt.rna at fragment load (bit-identical math).
//   smem = 4 x 128 x 36 x 4 = 73728 B dynamic; occupancy stays register-bound.
// ---------------------------------------------------------------------------
#define PJ_LDA 36   // 32 + 4 pad (float4-aligned, conflict-free fragments)
#define PJ_SMEM (4 * 128 * PJ_LDA * 4)   // 73728 B

__global__ __launch_bounds__(256)
void proj_mma_kernel(const float* __restrict__ Wp,
                     const float* __restrict__ bp,
                     float* __restrict__ out) {
    extern __shared__ uint32_t psm[];
    uint32_t* Ab[2] = { psm,                  psm + 2 * 128 * PJ_LDA };
    uint32_t* Bb[2] = { psm + 128 * PJ_LDA,   psm + 3 * 128 * PJ_LDA };

    const int tid  = threadIdx.x;
    const int wid  = tid >> 5;
    const int lane = tid & 31;
    const int row0 = blockIdx.x * 128;
    const int col0 = blockIdx.y * 128;

    const uint32_t smem_u32 = (uint32_t)__cvta_generic_to_shared(psm);
    const uint32_t aoff[2] = { smem_u32,                         smem_u32 + 2 * 128 * PJ_LDA * 4 };
    const uint32_t boff[2] = { smem_u32 + 128 * PJ_LDA * 4,      smem_u32 + 3 * 128 * PJ_LDA * 4 };

    const int warp_m = (wid & 1) * 64;   // 0 or 64
    const int warp_n = (wid >> 1) * 32;  // 0,32,64,96

    // stage tile kt into buffer buf (raw fp32 via cp.async), one commit group
    auto stage = [&](int kt, int buf) {
        const int k0 = kt * 32;
#pragma unroll
        for (int it = 0; it < 4; it++) {
            const int lin = it * 1024 + tid * 4;   // 0..4095
            const int r = lin >> 5, cc = lin & 31;
            cp_async16(aoff[buf] + (uint32_t)(r * PJ_LDA + cc) * 4,
                       &g_AO[(size_t)(row0 + r) * EE + k0 + cc]);
            cp_async16(boff[buf] + (uint32_t)(r * PJ_LDA + cc) * 4,
                       &Wp[(size_t)(col0 + r) * EE + k0 + cc]);
        }
        CP_COMMIT();
    };

    float c[4][4][4];   // [m16][n8][frag]
#pragma unroll
    for (int m = 0; m < 4; m++)
#pragma unroll
        for (int n = 0; n < 4; n++)
#pragma unroll
            for (int f = 0; f < 4; f++) c[m][n][f] = 0.f;

    const int lrow = lane >> 2;    // 0..7
    const int lcol = lane & 3;     // 0..3

    stage(0, 0);
    stage(1, 1);

    for (int kt = 0; kt < EE / 32; kt++) {
        if (kt < EE / 32 - 1) { CP_WAIT(1); } else { CP_WAIT(0); }
        __syncthreads();
        const int cur = kt & 1;
        const uint32_t* As = Ab[cur];
        const uint32_t* Bs = Bb[cur];

#pragma unroll
        for (int ks = 0; ks < 4; ks++) {
            const int kk = ks * 8;
            uint32_t a[4][4], b[4][2];
#pragma unroll
            for (int m = 0; m < 4; m++) {
                const int ar = warp_m + m * 16 + lrow;
                a[m][0] = f2tf32(__uint_as_float(As[ar * PJ_LDA + kk + lcol]));
                a[m][1] = f2tf32(__uint_as_float(As[(ar + 8) * PJ_LDA + kk + lcol]));
                a[m][2] = f2tf32(__uint_as_float(As[ar * PJ_LDA + kk + 4 + lcol]));
                a[m][3] = f2tf32(__uint_as_float(As[(ar + 8) * PJ_LDA + kk + 4 + lcol]));
            }
#pragma unroll
            for (int n = 0; n < 4; n++) {
                const int br = warp_n + n * 8 + lrow;
                b[n][0] = f2tf32(__uint_as_float(Bs[br * PJ_LDA + kk + lcol]));
                b[n][1] = f2tf32(__uint_as_float(Bs[br * PJ_LDA + kk + 4 + lcol]));
            }
#pragma unroll
            for (int m = 0; m < 4; m++)
#pragma unroll
                for (int n = 0; n < 4; n++)
                    mma_tf32_16x8x8(c[m][n][0], c[m][n][1], c[m][n][2], c[m][n][3],
                                    a[m][0], a[m][1], a[m][2], a[m][3],
                                    b[n][0], b[n][1]);
        }

        __syncthreads();   // all warps done reading buf[cur] before refill
        if (kt + 2 < EE / 32) stage(kt + 2, cur);
    }

    // epilogue: c frag rows = lane/4 (+8), cols = 2*(lane%4) (+1)
#pragma unroll
    for (int m = 0; m < 4; m++) {
#pragma unroll
        for (int n = 0; n < 4; n++) {
            const int col = col0 + warp_n + n * 8 + 2 * lcol;
            const int r1  = row0 + warp_m + m * 16 + lrow;
            const float b0 = bp[col], b1 = bp[col + 1];
            float2 o0 = make_float2(c[m][n][0] + b0, c[m][n][1] + b1);
            float2 o1 = make_float2(c[m][n][2] + b0, c[m][n][3] + b1);
            *(float2*)&out[(size_t)r1 * EE + col]       = o0;
            *(float2*)&out[(size_t)(r1 + 8) * EE + col] = o1;
        }
    }
}

// ---------------------------------------------------------------------------
// Launch
// ---------------------------------------------------------------------------
extern "C" void kernel_launch(void* const* d_in, const int* in_sizes, int n_in,
                              void* d_out, int out_size) {
    const float* x  = (const float*)d_in[0];
    const float* Wq = (const float*)d_in[1];
    const float* bq = (const float*)d_in[2];
    const float* Wp = (const float*)d_in[3];
    const float* bp = (const float*)d_in[4];
    float* out = (float*)d_out;

    cudaFuncSetAttribute(qkv_mma_kernel,  cudaFuncAttributeMaxDynamicSharedMemorySize, QK_SMEM);
    cudaFuncSetAttribute(attn_mma_kernel, cudaFuncAttributeMaxDynamicSharedMemorySize, AT_SMEM);
    cudaFuncSetAttribute(proj_mma_kernel, cudaFuncAttributeMaxDynamicSharedMemorySize, PJ_SMEM);

    qkv_mma_kernel<<<dim3(BT / 128, HH), 256, QK_SMEM>>>(x, Wq, bq);
    attn_mma_kernel<<<dim3(TT / 64, BB * HH), 128, AT_SMEM>>>();
    proj_mma_kernel<<<dim3(BT / 128, EE / 128), 256, PJ_SMEM>>>(Wp, bp, out);
}